// round 4
// baseline (speedup 1.0000x reference)
#include <cuda_runtime.h>
#include <cuda_bf16.h>
#include <cstdint>

#define D 128
#define MAXN 50000
#define MAXE 800000

// Scratch (allocation-free)
__device__ float          g_H[MAXN * D];                    // fp32 residual H
__device__ __nv_bfloat16  g_Hh[MAXN * D];                   // H hi bf16
__device__ __nv_bfloat16  g_Hl[MAXN * D];                   // H lo bf16
__device__ __nv_bfloat16  g_AGGh[MAXN * D];                 // AGG (or x) hi
__device__ __nv_bfloat16  g_AGGl[MAXN * D];                 // AGG (or x) lo
__device__ __nv_bfloat16  g_Wh[7 * D * D];                  // transposed [n][k] hi
__device__ __nv_bfloat16  g_Wl[7 * D * D];                  // transposed [n][k] lo
__device__ int g_cnt[MAXN];
__device__ int g_row_ptr[MAXN + 1];
__device__ int g_cursor[MAXN];
__device__ int g_adj[MAXE];

// ---------------- helpers ----------------

__device__ __forceinline__ void split_pack2(float x, float y,
                                            uint32_t& hi, uint32_t& lo)
{
    __nv_bfloat16 hx = __float2bfloat16(x);
    __nv_bfloat16 hy = __float2bfloat16(y);
    __nv_bfloat16 lx = __float2bfloat16(x - __bfloat162float(hx));
    __nv_bfloat16 ly = __float2bfloat16(y - __bfloat162float(hy));
    __nv_bfloat162 h2 = __halves2bfloat162(hx, hy);
    __nv_bfloat162 l2 = __halves2bfloat162(lx, ly);
    hi = *reinterpret_cast<uint32_t*>(&h2);
    lo = *reinterpret_cast<uint32_t*>(&l2);
}

__device__ __forceinline__ void mma16816(float* d,
    uint32_t a0, uint32_t a1, uint32_t a2, uint32_t a3,
    uint32_t b0, uint32_t b1)
{
    asm volatile(
        "mma.sync.aligned.m16n8k16.row.col.f32.bf16.bf16.f32 "
        "{%0,%1,%2,%3}, {%4,%5,%6,%7}, {%8,%9}, {%0,%1,%2,%3};\n"
        : "+f"(d[0]), "+f"(d[1]), "+f"(d[2]), "+f"(d[3])
        : "r"(a0), "r"(a1), "r"(a2), "r"(a3), "r"(b0), "r"(b1));
}

// ---------------- conversion kernels ----------------

// W (7 DxD matrices) -> transposed [n][k] hi/lo bf16
__global__ void __launch_bounds__(256) convert_w_kernel(
    const float* __restrict__ fw, const float* __restrict__ wrel,
    const float* __restrict__ wroot,
    __nv_bfloat16* __restrict__ Wh, __nv_bfloat16* __restrict__ Wl)
{
    int idx = blockIdx.x * 256 + threadIdx.x;   // 7*16384 threads
    if (idx >= 7 * D * D) return;
    int s = idx >> 14;
    int r = idx & 16383;
    int k = r >> 7;
    int n = r & 127;
    const float* srcm = (s == 0) ? fw
                      : (s < 4)  ? wrel + (size_t)(s - 1) * D * D
                                 : wroot + (size_t)(s - 4) * D * D;
    float v = srcm[k * D + n];
    __nv_bfloat16 h = __float2bfloat16(v);
    __nv_bfloat16 l = __float2bfloat16(v - __bfloat162float(h));
    Wh[(size_t)s * D * D + n * D + k] = h;
    Wl[(size_t)s * D * D + n * D + k] = l;
}

// x fp32 -> hi/lo bf16
__global__ void __launch_bounds__(256) convert_x_kernel(
    const float* __restrict__ x,
    __nv_bfloat16* __restrict__ Xh, __nv_bfloat16* __restrict__ Xl, int n4)
{
    int i = blockIdx.x * 256 + threadIdx.x;
    if (i >= n4) return;
    float4 v = ((const float4*)x)[i];
    uint2 h, l;
    split_pack2(v.x, v.y, h.x, l.x);
    split_pack2(v.z, v.w, h.y, l.y);
    ((uint2*)Xh)[i] = h;
    ((uint2*)Xl)[i] = l;
}

// ---------------- CSR build ----------------

__global__ void __launch_bounds__(256) zero_int_kernel(int* __restrict__ p, int n) {
    int i = blockIdx.x * blockDim.x + threadIdx.x;
    for (; i < n; i += gridDim.x * blockDim.x) p[i] = 0;
}

__global__ void __launch_bounds__(256) hist_kernel(
    const int* __restrict__ dst, int* __restrict__ cnt, int E)
{
    int i = blockIdx.x * blockDim.x + threadIdx.x;
    for (; i < E; i += gridDim.x * blockDim.x)
        atomicAdd(&cnt[dst[i]], 1);
}

__global__ void __launch_bounds__(1024) scan_kernel(
    const int* __restrict__ cnt, int* __restrict__ row_ptr,
    int* __restrict__ cursor, int n)
{
    __shared__ int warp_sums[32];
    int tid = threadIdx.x;
    int chunk = (n + 1023) / 1024;
    int beg = tid * chunk;
    int end = min(beg + chunk, n);

    int local = 0;
    for (int i = beg; i < end; i++) local += cnt[i];

    int lane = tid & 31, w = tid >> 5;
    int v = local;
    #pragma unroll
    for (int o = 1; o < 32; o <<= 1) {
        int t = __shfl_up_sync(~0u, v, o);
        if (lane >= o) v += t;
    }
    if (lane == 31) warp_sums[w] = v;
    __syncthreads();
    if (w == 0) {
        int s = warp_sums[lane];
        #pragma unroll
        for (int o = 1; o < 32; o <<= 1) {
            int t = __shfl_up_sync(~0u, s, o);
            if (lane >= o) s += t;
        }
        warp_sums[lane] = s;
    }
    __syncthreads();

    int excl = v - local + (w > 0 ? warp_sums[w - 1] : 0);
    int run = excl;
    for (int i = beg; i < end; i++) {
        row_ptr[i] = run;
        cursor[i]  = run;
        run += cnt[i];
    }
    if (tid == 1023) row_ptr[n] = run;
}

__global__ void __launch_bounds__(256) fill_kernel(
    const int* __restrict__ src, const int* __restrict__ dst,
    int* __restrict__ cursor, int* __restrict__ adj, int E)
{
    int i = blockIdx.x * blockDim.x + threadIdx.x;
    for (; i < E; i += gridDim.x * blockDim.x) {
        int p = atomicAdd(&cursor[dst[i]], 1);
        adj[p] = src[i];
    }
}

// ---------------- gather-aggregate -> hi/lo bf16 ----------------

__global__ void __launch_bounds__(256) aggregate_kernel(
    const float* __restrict__ H, const int* __restrict__ row_ptr,
    const int* __restrict__ adj,
    __nv_bfloat16* __restrict__ AGGh, __nv_bfloat16* __restrict__ AGGl, int N)
{
    int node = (blockIdx.x * blockDim.x + threadIdx.x) >> 5;
    int lane = threadIdx.x & 31;
    if (node >= N) return;
    int beg = __ldg(row_ptr + node);
    int end = __ldg(row_ptr + node + 1);

    float4 acc = make_float4(0.f, 0.f, 0.f, 0.f);
    int e = beg;
    for (; e + 4 <= end; e += 4) {
        int s0 = __ldg(adj + e + 0);
        int s1 = __ldg(adj + e + 1);
        int s2 = __ldg(adj + e + 2);
        int s3 = __ldg(adj + e + 3);
        float4 v0 = __ldg((const float4*)(H + (size_t)s0 * D) + lane);
        float4 v1 = __ldg((const float4*)(H + (size_t)s1 * D) + lane);
        float4 v2 = __ldg((const float4*)(H + (size_t)s2 * D) + lane);
        float4 v3 = __ldg((const float4*)(H + (size_t)s3 * D) + lane);
        acc.x += v0.x + v1.x + v2.x + v3.x;
        acc.y += v0.y + v1.y + v2.y + v3.y;
        acc.z += v0.z + v1.z + v2.z + v3.z;
        acc.w += v0.w + v1.w + v2.w + v3.w;
    }
    for (; e < end; e++) {
        int s = __ldg(adj + e);
        float4 v = __ldg((const float4*)(H + (size_t)s * D) + lane);
        acc.x += v.x; acc.y += v.y; acc.z += v.z; acc.w += v.w;
    }
    uint2 h, l;
    split_pack2(acc.x, acc.y, h.x, l.x);
    split_pack2(acc.z, acc.w, h.y, l.y);
    ((uint2*)(AGGh + (size_t)node * D))[lane] = h;
    ((uint2*)(AGGl + (size_t)node * D))[lane] = l;
}

// ---------------- tensor-core GEMM (bf16x3 split) ----------------
// Block: 256 threads = 8 warps (4x2 warp grid), tile 128 rows x 128 cols.
// Each warp: 32x64 (2 m-frags x 8 n-frags of m16n8k16).
// Terms accumulated into one fp32 acc:
//   single: A1h*W1h + A1l*W1h + A1h*W1l
//   dual  : + A2h*W2h + A2l*W2h + A2h*W2l
// W is pre-transposed [n][k] so B fragments are contiguous 2xbf16 loads.

#define SKA 72   // smem row stride in bf16 (64 + 8 pad)

template <bool DUAL, bool WRITE_BF16>
__global__ void __launch_bounds__(256, 2) gemm_mma(
    const __nv_bfloat16* __restrict__ A1h, const __nv_bfloat16* __restrict__ A1l,
    const __nv_bfloat16* __restrict__ W1h, const __nv_bfloat16* __restrict__ W1l,
    const __nv_bfloat16* __restrict__ A2h, const __nv_bfloat16* __restrict__ A2l,
    const __nv_bfloat16* __restrict__ W2h, const __nv_bfloat16* __restrict__ W2l,
    const float* __restrict__ bias, const float* __restrict__ Hres,
    float* __restrict__ out,
    __nv_bfloat16* __restrict__ OutH, __nv_bfloat16* __restrict__ OutL, int N)
{
    __shared__ __align__(16) __nv_bfloat16 sA[128][SKA];
    __shared__ __align__(16) __nv_bfloat16 sB[128][SKA];

    int tid = threadIdx.x;
    int lane = tid & 31, w = tid >> 5;
    int warp_m = w & 3;        // 0..3 -> rows warp_m*32
    int warp_n = w >> 2;       // 0..1 -> cols warp_n*64
    int g = lane >> 2, tg = lane & 3;
    int row0 = blockIdx.x * 128;

    float acc[2][8][4];
    #pragma unroll
    for (int mf = 0; mf < 2; mf++)
        #pragma unroll
        for (int nf = 0; nf < 8; nf++)
            #pragma unroll
            for (int c = 0; c < 4; c++) acc[mf][nf][c] = 0.f;

    const __nv_bfloat16* As[6] = { A1h, A1l, A1h, A2h, A2l, A2h };
    const __nv_bfloat16* Bs[6] = { W1h, W1h, W1l, W2h, W2h, W2l };
    const int NT = DUAL ? 6 : 3;

    const uint32_t* pA = (const uint32_t*)&sA[0][0];  // row stride 36 u32
    const uint32_t* pB = (const uint32_t*)&sB[0][0];

    #pragma unroll 1
    for (int t = 0; t < NT; t++) {
        const uint4* Ag = (const uint4*)As[t];
        const uint4* Bg = (const uint4*)Bs[t];
        #pragma unroll 1
        for (int ch = 0; ch < 2; ch++) {   // K chunks of 64
            // load A chunk (128 rows x 64 bf16) and B chunk
            #pragma unroll
            for (int i = 0; i < 4; i++) {
                int idx = tid + i * 256;
                int r = idx >> 3, c = idx & 7;
                uint4 va = make_uint4(0, 0, 0, 0);
                int gr = row0 + r;
                if (gr < N) va = Ag[gr * 16 + ch * 8 + c];
                *(uint4*)&sA[r][c * 8] = va;
                uint4 vb = Bg[r * 16 + ch * 8 + c];
                *(uint4*)&sB[r][c * 8] = vb;
            }
            __syncthreads();
            #pragma unroll
            for (int ks = 0; ks < 4; ks++) {
                uint32_t bfr[8][2];
                #pragma unroll
                for (int nf = 0; nf < 8; nf++) {
                    int n = warp_n * 64 + nf * 8 + g;
                    bfr[nf][0] = pB[n * 36 + ks * 8 + tg];
                    bfr[nf][1] = pB[n * 36 + ks * 8 + tg + 4];
                }
                #pragma unroll
                for (int mf = 0; mf < 2; mf++) {
                    int r0 = warp_m * 32 + mf * 16 + g;
                    uint32_t a0 = pA[r0 * 36 + ks * 8 + tg];
                    uint32_t a1 = pA[(r0 + 8) * 36 + ks * 8 + tg];
                    uint32_t a2 = pA[r0 * 36 + ks * 8 + tg + 4];
                    uint32_t a3 = pA[(r0 + 8) * 36 + ks * 8 + tg + 4];
                    #pragma unroll
                    for (int nf = 0; nf < 8; nf++)
                        mma16816(acc[mf][nf], a0, a1, a2, a3,
                                 bfr[nf][0], bfr[nf][1]);
                }
            }
            __syncthreads();
        }
    }

    // epilogue
    #pragma unroll
    for (int mf = 0; mf < 2; mf++) {
        #pragma unroll
        for (int half = 0; half < 2; half++) {
            int row = row0 + warp_m * 32 + mf * 16 + g + half * 8;
            if (row >= N) continue;
            #pragma unroll
            for (int nf = 0; nf < 8; nf++) {
                int col = warp_n * 64 + nf * 8 + tg * 2;
                float cx = acc[mf][nf][half * 2 + 0] + __ldg(bias + col);
                float cy = acc[mf][nf][half * 2 + 1] + __ldg(bias + col + 1);
                if (DUAL) {
                    float2 h2 = *(const float2*)(Hres + (size_t)row * D + col);
                    cx = fmaxf(cx, 0.f) + h2.x;
                    cy = fmaxf(cy, 0.f) + h2.y;
                }
                *(float2*)(out + (size_t)row * D + col) = make_float2(cx, cy);
                if (WRITE_BF16) {
                    uint32_t h, l;
                    split_pack2(cx, cy, h, l);
                    *(uint32_t*)(OutH + (size_t)row * D + col) = h;
                    *(uint32_t*)(OutL + (size_t)row * D + col) = l;
                }
            }
        }
    }
}

// ---------------- launch ----------------

extern "C" void kernel_launch(void* const* d_in, const int* in_sizes, int n_in,
                              void* d_out, int out_size)
{
    const float* x       = (const float*)d_in[0];
    const int*   ei      = (const int*)  d_in[1];
    const float* in_fc_w = (const float*)d_in[2];
    const float* in_fc_b = (const float*)d_in[3];
    const float* w_rel   = (const float*)d_in[4];
    const float* b_rel   = (const float*)d_in[5];
    const float* w_root  = (const float*)d_in[6];

    int N = in_sizes[0] / D;
    int E = in_sizes[1] / 2;
    const int* src = ei;
    const int* dst = ei + E;

    float* H;
    __nv_bfloat16 *Hh, *Hl, *AGGh, *AGGl, *Wh, *Wl;
    int *cnt, *row_ptr, *cursor, *adj;
    cudaGetSymbolAddress((void**)&H,       g_H);
    cudaGetSymbolAddress((void**)&Hh,      g_Hh);
    cudaGetSymbolAddress((void**)&Hl,      g_Hl);
    cudaGetSymbolAddress((void**)&AGGh,    g_AGGh);
    cudaGetSymbolAddress((void**)&AGGl,    g_AGGl);
    cudaGetSymbolAddress((void**)&Wh,      g_Wh);
    cudaGetSymbolAddress((void**)&Wl,      g_Wl);
    cudaGetSymbolAddress((void**)&cnt,     g_cnt);
    cudaGetSymbolAddress((void**)&row_ptr, g_row_ptr);
    cudaGetSymbolAddress((void**)&cursor,  g_cursor);
    cudaGetSymbolAddress((void**)&adj,     g_adj);

    int gblocks = (N + 127) / 128;
    int eblocks = (E + 255) / 256;
    int ablocks = (N * 32 + 255) / 256;

    // one-time conversions
    convert_w_kernel<<<(7 * D * D + 255) / 256, 256>>>(in_fc_w, w_rel, w_root, Wh, Wl);
    convert_x_kernel<<<(N * D / 4 + 255) / 256, 256>>>(x, AGGh, AGGl, N * D / 4);

    // CSR build (dst-sorted adjacency)
    zero_int_kernel<<<(N + 255) / 256, 256>>>(cnt, N);
    hist_kernel<<<eblocks, 256>>>(dst, cnt, E);
    scan_kernel<<<1, 1024>>>(cnt, row_ptr, cursor, N);
    fill_kernel<<<eblocks, 256>>>(src, dst, cursor, adj, E);

    // h = x @ in_fc_w + in_fc_b   (A1 = x hi/lo staged in AGG buffers)
    gemm_mma<false, true><<<gblocks, 256>>>(
        AGGh, AGGl, Wh, Wl,
        nullptr, nullptr, nullptr, nullptr,
        in_fc_b, nullptr, H, Hh, Hl, N);

    for (int l = 0; l < 3; l++) {
        aggregate_kernel<<<ablocks, 256>>>(H, row_ptr, adj, AGGh, AGGl, N);
        const __nv_bfloat16* W1h = Wh + (size_t)(1 + l) * D * D;
        const __nv_bfloat16* W1l = Wl + (size_t)(1 + l) * D * D;
        const __nv_bfloat16* W2h = Wh + (size_t)(4 + l) * D * D;
        const __nv_bfloat16* W2l = Wl + (size_t)(4 + l) * D * D;
        if (l < 2) {
            gemm_mma<true, true><<<gblocks, 256>>>(
                AGGh, AGGl, W1h, W1l, Hh, Hl, W2h, W2l,
                b_rel + (size_t)l * D, H, H, Hh, Hl, N);
        } else {
            gemm_mma<true, false><<<gblocks, 256>>>(
                AGGh, AGGl, W1h, W1l, Hh, Hl, W2h, W2l,
                b_rel + (size_t)l * D, H, (float*)d_out, nullptr, nullptr, N);
        }
    }
}

// round 5
// speedup vs baseline: 1.2683x; 1.2683x over previous
#include <cuda_runtime.h>
#include <cuda_bf16.h>
#include <cstdint>

#define D 128
#define MAXN 50000
#define MAXE 800000

// Scratch (allocation-free)
__device__ float          g_H[MAXN * D];
__device__ __nv_bfloat16  g_Hh[MAXN * D];
__device__ __nv_bfloat16  g_Hl[MAXN * D];
__device__ __nv_bfloat16  g_AGGh[MAXN * D];
__device__ __nv_bfloat16  g_AGGl[MAXN * D];
__device__ __nv_bfloat16  g_Wh[7 * D * D];     // transposed [n][k] hi
__device__ __nv_bfloat16  g_Wl[7 * D * D];     // transposed [n][k] lo
__device__ int g_cnt[MAXN];
__device__ int g_row_ptr[MAXN + 1];
__device__ int g_cursor[MAXN];
__device__ int g_adj[MAXE];

// ---------------- helpers ----------------

__device__ __forceinline__ void split_pack2(float x, float y,
                                            uint32_t& hi, uint32_t& lo)
{
    __nv_bfloat16 hx = __float2bfloat16(x);
    __nv_bfloat16 hy = __float2bfloat16(y);
    __nv_bfloat16 lx = __float2bfloat16(x - __bfloat162float(hx));
    __nv_bfloat16 ly = __float2bfloat16(y - __bfloat162float(hy));
    __nv_bfloat162 h2 = __halves2bfloat162(hx, hy);
    __nv_bfloat162 l2 = __halves2bfloat162(lx, ly);
    hi = *reinterpret_cast<uint32_t*>(&h2);
    lo = *reinterpret_cast<uint32_t*>(&l2);
}

__device__ __forceinline__ void mma16816(float* d,
    uint32_t a0, uint32_t a1, uint32_t a2, uint32_t a3,
    uint32_t b0, uint32_t b1)
{
    asm volatile(
        "mma.sync.aligned.m16n8k16.row.col.f32.bf16.bf16.f32 "
        "{%0,%1,%2,%3}, {%4,%5,%6,%7}, {%8,%9}, {%0,%1,%2,%3};\n"
        : "+f"(d[0]), "+f"(d[1]), "+f"(d[2]), "+f"(d[3])
        : "r"(a0), "r"(a1), "r"(a2), "r"(a3), "r"(b0), "r"(b1));
}

__device__ __forceinline__ void cp_async16(void* smem, const void* gmem, bool pred)
{
    uint32_t s = (uint32_t)__cvta_generic_to_shared(smem);
    int sz = pred ? 16 : 0;
    asm volatile("cp.async.cg.shared.global [%0], [%1], 16, %2;\n"
                 :: "r"(s), "l"(gmem), "r"(sz));
}
__device__ __forceinline__ void cp_commit() {
    asm volatile("cp.async.commit_group;\n");
}
template <int N_>
__device__ __forceinline__ void cp_wait() {
    asm volatile("cp.async.wait_group %0;\n" :: "n"(N_));
}

// ---------------- conversion kernels ----------------

__global__ void __launch_bounds__(256) convert_w_kernel(
    const float* __restrict__ fw, const float* __restrict__ wrel,
    const float* __restrict__ wroot,
    __nv_bfloat16* __restrict__ Wh, __nv_bfloat16* __restrict__ Wl)
{
    int idx = blockIdx.x * 256 + threadIdx.x;
    if (idx >= 7 * D * D) return;
    int s = idx >> 14;
    int r = idx & 16383;
    int k = r >> 7;
    int n = r & 127;
    const float* srcm = (s == 0) ? fw
                      : (s < 4)  ? wrel + (size_t)(s - 1) * D * D
                                 : wroot + (size_t)(s - 4) * D * D;
    float v = srcm[k * D + n];
    __nv_bfloat16 h = __float2bfloat16(v);
    __nv_bfloat16 l = __float2bfloat16(v - __bfloat162float(h));
    Wh[(size_t)s * D * D + n * D + k] = h;
    Wl[(size_t)s * D * D + n * D + k] = l;
}

__global__ void __launch_bounds__(256) convert_x_kernel(
    const float* __restrict__ x,
    __nv_bfloat16* __restrict__ Xh, __nv_bfloat16* __restrict__ Xl, int n4)
{
    int i = blockIdx.x * 256 + threadIdx.x;
    if (i >= n4) return;
    float4 v = ((const float4*)x)[i];
    uint2 h, l;
    split_pack2(v.x, v.y, h.x, l.x);
    split_pack2(v.z, v.w, h.y, l.y);
    ((uint2*)Xh)[i] = h;
    ((uint2*)Xl)[i] = l;
}

// ---------------- CSR build ----------------

__global__ void __launch_bounds__(256) zero_int_kernel(int* __restrict__ p, int n) {
    int i = blockIdx.x * blockDim.x + threadIdx.x;
    for (; i < n; i += gridDim.x * blockDim.x) p[i] = 0;
}

__global__ void __launch_bounds__(256) hist_kernel(
    const int* __restrict__ dst, int* __restrict__ cnt, int E)
{
    int i = blockIdx.x * blockDim.x + threadIdx.x;
    for (; i < E; i += gridDim.x * blockDim.x)
        atomicAdd(&cnt[dst[i]], 1);
}

__global__ void __launch_bounds__(1024) scan_kernel(
    const int* __restrict__ cnt, int* __restrict__ row_ptr,
    int* __restrict__ cursor, int n)
{
    __shared__ int warp_sums[32];
    int tid = threadIdx.x;
    int chunk = (n + 1023) / 1024;
    int beg = tid * chunk;
    int end = min(beg + chunk, n);

    int local = 0;
    for (int i = beg; i < end; i++) local += cnt[i];

    int lane = tid & 31, w = tid >> 5;
    int v = local;
    #pragma unroll
    for (int o = 1; o < 32; o <<= 1) {
        int t = __shfl_up_sync(~0u, v, o);
        if (lane >= o) v += t;
    }
    if (lane == 31) warp_sums[w] = v;
    __syncthreads();
    if (w == 0) {
        int s = warp_sums[lane];
        #pragma unroll
        for (int o = 1; o < 32; o <<= 1) {
            int t = __shfl_up_sync(~0u, s, o);
            if (lane >= o) s += t;
        }
        warp_sums[lane] = s;
    }
    __syncthreads();

    int excl = v - local + (w > 0 ? warp_sums[w - 1] : 0);
    int run = excl;
    for (int i = beg; i < end; i++) {
        row_ptr[i] = run;
        cursor[i]  = run;
        run += cnt[i];
    }
    if (tid == 1023) row_ptr[n] = run;
}

__global__ void __launch_bounds__(256) fill_kernel(
    const int* __restrict__ src, const int* __restrict__ dst,
    int* __restrict__ cursor, int* __restrict__ adj, int E)
{
    int i = blockIdx.x * blockDim.x + threadIdx.x;
    for (; i < E; i += gridDim.x * blockDim.x) {
        int p = atomicAdd(&cursor[dst[i]], 1);
        adj[p] = src[i];
    }
}

// ---------------- gather-aggregate -> hi/lo bf16 ----------------

__global__ void __launch_bounds__(256) aggregate_kernel(
    const float* __restrict__ H, const int* __restrict__ row_ptr,
    const int* __restrict__ adj,
    __nv_bfloat16* __restrict__ AGGh, __nv_bfloat16* __restrict__ AGGl, int N)
{
    int node = (blockIdx.x * blockDim.x + threadIdx.x) >> 5;
    int lane = threadIdx.x & 31;
    if (node >= N) return;
    int beg = __ldg(row_ptr + node);
    int end = __ldg(row_ptr + node + 1);

    float4 acc = make_float4(0.f, 0.f, 0.f, 0.f);
    int e = beg;
    for (; e + 4 <= end; e += 4) {
        int s0 = __ldg(adj + e + 0);
        int s1 = __ldg(adj + e + 1);
        int s2 = __ldg(adj + e + 2);
        int s3 = __ldg(adj + e + 3);
        float4 v0 = __ldg((const float4*)(H + (size_t)s0 * D) + lane);
        float4 v1 = __ldg((const float4*)(H + (size_t)s1 * D) + lane);
        float4 v2 = __ldg((const float4*)(H + (size_t)s2 * D) + lane);
        float4 v3 = __ldg((const float4*)(H + (size_t)s3 * D) + lane);
        acc.x += v0.x + v1.x + v2.x + v3.x;
        acc.y += v0.y + v1.y + v2.y + v3.y;
        acc.z += v0.z + v1.z + v2.z + v3.z;
        acc.w += v0.w + v1.w + v2.w + v3.w;
    }
    for (; e < end; e++) {
        int s = __ldg(adj + e);
        float4 v = __ldg((const float4*)(H + (size_t)s * D) + lane);
        acc.x += v.x; acc.y += v.y; acc.z += v.z; acc.w += v.w;
    }
    uint2 h, l;
    split_pack2(acc.x, acc.y, h.x, l.x);
    split_pack2(acc.z, acc.w, h.y, l.y);
    ((uint2*)(AGGh + (size_t)node * D))[lane] = h;
    ((uint2*)(AGGl + (size_t)node * D))[lane] = l;
}

// ---------------- tensor-core GEMM (bf16x3, cp.async double-buffered) ----
// View the multi-term GEMM as one long-K GEMM: NC chunks of K=32.
// chunk c: term t = c>>2 uses (As[t], Bs[t]) at column offset (c&3)*32.
// Block: 256 threads = 8 warps (4x2), tile 128x128. Warp: 32x64.
// smem per stage: A 128x(32+8pad) bf16 + B same = 20KB; 2 stages = 40KB.

#define SKW 40            // bf16 row stride (32 data + 8 pad)
#define SKU 20            // same in u32

template <bool DUAL, bool WRITE_BF16>
__global__ void __launch_bounds__(256, 2) gemm_mma(
    const __nv_bfloat16* __restrict__ A1h, const __nv_bfloat16* __restrict__ A1l,
    const __nv_bfloat16* __restrict__ W1h, const __nv_bfloat16* __restrict__ W1l,
    const __nv_bfloat16* __restrict__ A2h, const __nv_bfloat16* __restrict__ A2l,
    const __nv_bfloat16* __restrict__ W2h, const __nv_bfloat16* __restrict__ W2l,
    const float* __restrict__ bias, const float* __restrict__ Hres,
    float* __restrict__ out,
    __nv_bfloat16* __restrict__ OutH, __nv_bfloat16* __restrict__ OutL, int N)
{
    __shared__ __align__(16) __nv_bfloat16 sA[2][128][SKW];
    __shared__ __align__(16) __nv_bfloat16 sB[2][128][SKW];

    int tid = threadIdx.x;
    int lane = tid & 31, w = tid >> 5;
    int warp_m = w & 3;
    int warp_n = w >> 2;
    int g = lane >> 2, tg = lane & 3;
    int row0 = blockIdx.x * 128;

    float acc[2][8][4];
    #pragma unroll
    for (int mf = 0; mf < 2; mf++)
        #pragma unroll
        for (int nf = 0; nf < 8; nf++)
            #pragma unroll
            for (int c = 0; c < 4; c++) acc[mf][nf][c] = 0.f;

    const __nv_bfloat16* As[6] = { A1h, A1l, A1h, A2h, A2l, A2h };
    const __nv_bfloat16* Bs[6] = { W1h, W1h, W1l, W2h, W2h, W2l };
    const int NC = DUAL ? 24 : 12;

    // per-thread prefetch coords: 2 units of 16B for A, 2 for B
    int pr = tid >> 2;            // row 0..63 (unit 0), +64 for unit 1
    int pc = tid & 3;             // 16B column group 0..3

    auto prefetch = [&](int c, int buf) {
        const __nv_bfloat16* Ag = As[c >> 2];
        const __nv_bfloat16* Bg = Bs[c >> 2];
        int koff = (c & 3) * 32 + pc * 8;
        #pragma unroll
        for (int i = 0; i < 2; i++) {
            int r = pr + i * 64;
            int gr = row0 + r;
            cp_async16(&sA[buf][r][pc * 8], Ag + (size_t)gr * D + koff, gr < N);
            cp_async16(&sB[buf][r][pc * 8], Bg + (size_t)r * D + koff, true);
        }
        cp_commit();
    };

    prefetch(0, 0);

    #pragma unroll 1
    for (int c = 0; c < NC; c++) {
        if (c + 1 < NC) {
            prefetch(c + 1, (c + 1) & 1);
            cp_wait<1>();
        } else {
            cp_wait<0>();
        }
        __syncthreads();

        const uint32_t* pA = (const uint32_t*)&sA[c & 1][0][0];
        const uint32_t* pB = (const uint32_t*)&sB[c & 1][0][0];

        #pragma unroll
        for (int ks = 0; ks < 2; ks++) {
            uint32_t bfr[8][2];
            #pragma unroll
            for (int nf = 0; nf < 8; nf++) {
                int n = warp_n * 64 + nf * 8 + g;
                bfr[nf][0] = pB[n * SKU + ks * 8 + tg];
                bfr[nf][1] = pB[n * SKU + ks * 8 + tg + 4];
            }
            #pragma unroll
            for (int mf = 0; mf < 2; mf++) {
                int r0 = warp_m * 32 + mf * 16 + g;
                uint32_t a0 = pA[r0 * SKU + ks * 8 + tg];
                uint32_t a1 = pA[(r0 + 8) * SKU + ks * 8 + tg];
                uint32_t a2 = pA[r0 * SKU + ks * 8 + tg + 4];
                uint32_t a3 = pA[(r0 + 8) * SKU + ks * 8 + tg + 4];
                #pragma unroll
                for (int nf = 0; nf < 8; nf++)
                    mma16816(acc[mf][nf], a0, a1, a2, a3,
                             bfr[nf][0], bfr[nf][1]);
            }
        }
        __syncthreads();
    }

    // epilogue
    #pragma unroll
    for (int mf = 0; mf < 2; mf++) {
        #pragma unroll
        for (int half = 0; half < 2; half++) {
            int row = row0 + warp_m * 32 + mf * 16 + g + half * 8;
            if (row >= N) continue;
            #pragma unroll
            for (int nf = 0; nf < 8; nf++) {
                int col = warp_n * 64 + nf * 8 + tg * 2;
                float cx = acc[mf][nf][half * 2 + 0] + __ldg(bias + col);
                float cy = acc[mf][nf][half * 2 + 1] + __ldg(bias + col + 1);
                if (DUAL) {
                    float2 h2 = *(const float2*)(Hres + (size_t)row * D + col);
                    cx = fmaxf(cx, 0.f) + h2.x;
                    cy = fmaxf(cy, 0.f) + h2.y;
                }
                *(float2*)(out + (size_t)row * D + col) = make_float2(cx, cy);
                if (WRITE_BF16) {
                    uint32_t h, l;
                    split_pack2(cx, cy, h, l);
                    *(uint32_t*)(OutH + (size_t)row * D + col) = h;
                    *(uint32_t*)(OutL + (size_t)row * D + col) = l;
                }
            }
        }
    }
}

// ---------------- launch ----------------

extern "C" void kernel_launch(void* const* d_in, const int* in_sizes, int n_in,
                              void* d_out, int out_size)
{
    const float* x       = (const float*)d_in[0];
    const int*   ei      = (const int*)  d_in[1];
    const float* in_fc_w = (const float*)d_in[2];
    const float* in_fc_b = (const float*)d_in[3];
    const float* w_rel   = (const float*)d_in[4];
    const float* b_rel   = (const float*)d_in[5];
    const float* w_root  = (const float*)d_in[6];

    int N = in_sizes[0] / D;
    int E = in_sizes[1] / 2;
    const int* src = ei;
    const int* dst = ei + E;

    float* H;
    __nv_bfloat16 *Hh, *Hl, *AGGh, *AGGl, *Wh, *Wl;
    int *cnt, *row_ptr, *cursor, *adj;
    cudaGetSymbolAddress((void**)&H,       g_H);
    cudaGetSymbolAddress((void**)&Hh,      g_Hh);
    cudaGetSymbolAddress((void**)&Hl,      g_Hl);
    cudaGetSymbolAddress((void**)&AGGh,    g_AGGh);
    cudaGetSymbolAddress((void**)&AGGl,    g_AGGl);
    cudaGetSymbolAddress((void**)&Wh,      g_Wh);
    cudaGetSymbolAddress((void**)&Wl,      g_Wl);
    cudaGetSymbolAddress((void**)&cnt,     g_cnt);
    cudaGetSymbolAddress((void**)&row_ptr, g_row_ptr);
    cudaGetSymbolAddress((void**)&cursor,  g_cursor);
    cudaGetSymbolAddress((void**)&adj,     g_adj);

    int gblocks = (N + 127) / 128;
    int eblocks = (E + 255) / 256;
    int ablocks = (N * 32 + 255) / 256;

    // one-time conversions
    convert_w_kernel<<<(7 * D * D + 255) / 256, 256>>>(in_fc_w, w_rel, w_root, Wh, Wl);
    convert_x_kernel<<<(N * D / 4 + 255) / 256, 256>>>(x, AGGh, AGGl, N * D / 4);

    // CSR build (dst-sorted adjacency)
    zero_int_kernel<<<(N + 255) / 256, 256>>>(cnt, N);
    hist_kernel<<<eblocks, 256>>>(dst, cnt, E);
    scan_kernel<<<1, 1024>>>(cnt, row_ptr, cursor, N);
    fill_kernel<<<eblocks, 256>>>(src, dst, cursor, adj, E);

    // h = x @ in_fc_w + in_fc_b
    gemm_mma<false, true><<<gblocks, 256>>>(
        AGGh, AGGl, Wh, Wl,
        nullptr, nullptr, nullptr, nullptr,
        in_fc_b, nullptr, H, Hh, Hl, N);

    for (int l = 0; l < 3; l++) {
        aggregate_kernel<<<ablocks, 256>>>(H, row_ptr, adj, AGGh, AGGl, N);
        const __nv_bfloat16* W1h = Wh + (size_t)(1 + l) * D * D;
        const __nv_bfloat16* W1l = Wl + (size_t)(1 + l) * D * D;
        const __nv_bfloat16* W2h = Wh + (size_t)(4 + l) * D * D;
        const __nv_bfloat16* W2l = Wl + (size_t)(4 + l) * D * D;
        if (l < 2) {
            gemm_mma<true, true><<<gblocks, 256>>>(
                AGGh, AGGl, W1h, W1l, Hh, Hl, W2h, W2l,
                b_rel + (size_t)l * D, H, H, Hh, Hl, N);
        } else {
            gemm_mma<true, false><<<gblocks, 256>>>(
                AGGh, AGGl, W1h, W1l, Hh, Hl, W2h, W2l,
                b_rel + (size_t)l * D, H, (float*)d_out, nullptr, nullptr, N);
        }
    }
}

// round 6
// speedup vs baseline: 1.2707x; 1.0019x over previous
#include <cuda_runtime.h>
#include <cuda_bf16.h>
#include <cstdint>

#define D 128
#define MAXN 50000
#define MAXE 800000

// Scratch (allocation-free)
__device__ float          g_H[MAXN * D];
__device__ __nv_bfloat16  g_Hh[MAXN * D];
__device__ __nv_bfloat16  g_Hl[MAXN * D];
__device__ __nv_bfloat16  g_AGGh[MAXN * D];
__device__ __nv_bfloat16  g_AGGl[MAXN * D];
__device__ __nv_bfloat16  g_Wh[7 * D * D];     // transposed [n][k] hi
__device__ __nv_bfloat16  g_Wl[7 * D * D];     // transposed [n][k] lo
__device__ int g_cnt[MAXN];
__device__ int g_row_ptr[MAXN + 1];
__device__ int g_cursor[MAXN];
__device__ int g_adj[MAXE];

// ---------------- helpers ----------------

__device__ __forceinline__ void split_pack2(float x, float y,
                                            uint32_t& hi, uint32_t& lo)
{
    __nv_bfloat16 hx = __float2bfloat16(x);
    __nv_bfloat16 hy = __float2bfloat16(y);
    __nv_bfloat16 lx = __float2bfloat16(x - __bfloat162float(hx));
    __nv_bfloat16 ly = __float2bfloat16(y - __bfloat162float(hy));
    __nv_bfloat162 h2 = __halves2bfloat162(hx, hy);
    __nv_bfloat162 l2 = __halves2bfloat162(lx, ly);
    hi = *reinterpret_cast<uint32_t*>(&h2);
    lo = *reinterpret_cast<uint32_t*>(&l2);
}

__device__ __forceinline__ void mma16816(float* d,
    uint32_t a0, uint32_t a1, uint32_t a2, uint32_t a3,
    uint32_t b0, uint32_t b1)
{
    asm volatile(
        "mma.sync.aligned.m16n8k16.row.col.f32.bf16.bf16.f32 "
        "{%0,%1,%2,%3}, {%4,%5,%6,%7}, {%8,%9}, {%0,%1,%2,%3};\n"
        : "+f"(d[0]), "+f"(d[1]), "+f"(d[2]), "+f"(d[3])
        : "r"(a0), "r"(a1), "r"(a2), "r"(a3), "r"(b0), "r"(b1));
}

__device__ __forceinline__ void ldsm_x4(uint32_t* r, uint32_t saddr)
{
    asm volatile(
        "ldmatrix.sync.aligned.m8n8.x4.shared.b16 {%0,%1,%2,%3}, [%4];\n"
        : "=r"(r[0]), "=r"(r[1]), "=r"(r[2]), "=r"(r[3]) : "r"(saddr));
}

__device__ __forceinline__ void cp_async16(void* smem, const void* gmem, bool pred)
{
    uint32_t s = (uint32_t)__cvta_generic_to_shared(smem);
    int sz = pred ? 16 : 0;
    asm volatile("cp.async.cg.shared.global [%0], [%1], 16, %2;\n"
                 :: "r"(s), "l"(gmem), "r"(sz));
}
__device__ __forceinline__ void cp_commit() {
    asm volatile("cp.async.commit_group;\n");
}
template <int N_>
__device__ __forceinline__ void cp_wait() {
    asm volatile("cp.async.wait_group %0;\n" :: "n"(N_));
}

// ---------------- conversion kernels ----------------

__global__ void __launch_bounds__(256) convert_w_kernel(
    const float* __restrict__ fw, const float* __restrict__ wrel,
    const float* __restrict__ wroot,
    __nv_bfloat16* __restrict__ Wh, __nv_bfloat16* __restrict__ Wl)
{
    int idx = blockIdx.x * 256 + threadIdx.x;
    if (idx >= 7 * D * D) return;
    int s = idx >> 14;
    int r = idx & 16383;
    int k = r >> 7;
    int n = r & 127;
    const float* srcm = (s == 0) ? fw
                      : (s < 4)  ? wrel + (size_t)(s - 1) * D * D
                                 : wroot + (size_t)(s - 4) * D * D;
    float v = srcm[k * D + n];
    __nv_bfloat16 h = __float2bfloat16(v);
    __nv_bfloat16 l = __float2bfloat16(v - __bfloat162float(h));
    Wh[(size_t)s * D * D + n * D + k] = h;
    Wl[(size_t)s * D * D + n * D + k] = l;
}

__global__ void __launch_bounds__(256) convert_x_kernel(
    const float* __restrict__ x,
    __nv_bfloat16* __restrict__ Xh, __nv_bfloat16* __restrict__ Xl, int n4)
{
    int i = blockIdx.x * 256 + threadIdx.x;
    if (i >= n4) return;
    float4 v = ((const float4*)x)[i];
    uint2 h, l;
    split_pack2(v.x, v.y, h.x, l.x);
    split_pack2(v.z, v.w, h.y, l.y);
    ((uint2*)Xh)[i] = h;
    ((uint2*)Xl)[i] = l;
}

// ---------------- CSR build ----------------

__global__ void __launch_bounds__(256) zero_int_kernel(int* __restrict__ p, int n) {
    int i = blockIdx.x * blockDim.x + threadIdx.x;
    for (; i < n; i += gridDim.x * blockDim.x) p[i] = 0;
}

__global__ void __launch_bounds__(256) hist_kernel(
    const int* __restrict__ dst, int* __restrict__ cnt, int E)
{
    int i = blockIdx.x * blockDim.x + threadIdx.x;
    for (; i < E; i += gridDim.x * blockDim.x)
        atomicAdd(&cnt[dst[i]], 1);
}

__global__ void __launch_bounds__(1024) scan_kernel(
    const int* __restrict__ cnt, int* __restrict__ row_ptr,
    int* __restrict__ cursor, int n)
{
    __shared__ int warp_sums[32];
    int tid = threadIdx.x;
    int chunk = (n + 1023) / 1024;
    int beg = tid * chunk;
    int end = min(beg + chunk, n);

    int local = 0;
    for (int i = beg; i < end; i++) local += cnt[i];

    int lane = tid & 31, w = tid >> 5;
    int v = local;
    #pragma unroll
    for (int o = 1; o < 32; o <<= 1) {
        int t = __shfl_up_sync(~0u, v, o);
        if (lane >= o) v += t;
    }
    if (lane == 31) warp_sums[w] = v;
    __syncthreads();
    if (w == 0) {
        int s = warp_sums[lane];
        #pragma unroll
        for (int o = 1; o < 32; o <<= 1) {
            int t = __shfl_up_sync(~0u, s, o);
            if (lane >= o) s += t;
        }
        warp_sums[lane] = s;
    }
    __syncthreads();

    int excl = v - local + (w > 0 ? warp_sums[w - 1] : 0);
    int run = excl;
    for (int i = beg; i < end; i++) {
        row_ptr[i] = run;
        cursor[i]  = run;
        run += cnt[i];
    }
    if (tid == 1023) row_ptr[n] = run;
}

__global__ void __launch_bounds__(256) fill_kernel(
    const int* __restrict__ src, const int* __restrict__ dst,
    int* __restrict__ cursor, int* __restrict__ adj, int E)
{
    int i = blockIdx.x * blockDim.x + threadIdx.x;
    for (; i < E; i += gridDim.x * blockDim.x) {
        int p = atomicAdd(&cursor[dst[i]], 1);
        adj[p] = src[i];
    }
}

// ---------------- gather-aggregate -> hi/lo bf16 ----------------

__global__ void __launch_bounds__(256) aggregate_kernel(
    const float* __restrict__ H, const int* __restrict__ row_ptr,
    const int* __restrict__ adj,
    __nv_bfloat16* __restrict__ AGGh, __nv_bfloat16* __restrict__ AGGl, int N)
{
    int node = (blockIdx.x * blockDim.x + threadIdx.x) >> 5;
    int lane = threadIdx.x & 31;
    if (node >= N) return;
    int beg = __ldg(row_ptr + node);
    int end = __ldg(row_ptr + node + 1);

    float4 acc = make_float4(0.f, 0.f, 0.f, 0.f);
    int e = beg;
    for (; e + 4 <= end; e += 4) {
        int s0 = __ldg(adj + e + 0);
        int s1 = __ldg(adj + e + 1);
        int s2 = __ldg(adj + e + 2);
        int s3 = __ldg(adj + e + 3);
        float4 v0 = __ldg((const float4*)(H + (size_t)s0 * D) + lane);
        float4 v1 = __ldg((const float4*)(H + (size_t)s1 * D) + lane);
        float4 v2 = __ldg((const float4*)(H + (size_t)s2 * D) + lane);
        float4 v3 = __ldg((const float4*)(H + (size_t)s3 * D) + lane);
        acc.x += v0.x + v1.x + v2.x + v3.x;
        acc.y += v0.y + v1.y + v2.y + v3.y;
        acc.z += v0.z + v1.z + v2.z + v3.z;
        acc.w += v0.w + v1.w + v2.w + v3.w;
    }
    for (; e < end; e++) {
        int s = __ldg(adj + e);
        float4 v = __ldg((const float4*)(H + (size_t)s * D) + lane);
        acc.x += v.x; acc.y += v.y; acc.z += v.z; acc.w += v.w;
    }
    uint2 h, l;
    split_pack2(acc.x, acc.y, h.x, l.x);
    split_pack2(acc.z, acc.w, h.y, l.y);
    ((uint2*)(AGGh + (size_t)node * D))[lane] = h;
    ((uint2*)(AGGl + (size_t)node * D))[lane] = l;
}

// ---------------- tensor-core GEMM (bf16x3, ldmatrix + cp.async) ----------
// Long-K view: NC chunks of K=32; chunk c uses term t=c>>2, k-offset (c&3)*32.
// Block 256 thr = 8 warps (4x2), tile 128x128; warp 32x64.
// Mainloop per chunk: 12 LDSM.x4 + 32 HMMA + 1 bar.

#define SKW 40            // bf16 row stride (32 data + 8 pad); 80B, 16B-aligned rows

template <bool DUAL, bool WRITE_BF16>
__global__ void __launch_bounds__(256, 2) gemm_mma(
    const __nv_bfloat16* __restrict__ A1h, const __nv_bfloat16* __restrict__ A1l,
    const __nv_bfloat16* __restrict__ W1h, const __nv_bfloat16* __restrict__ W1l,
    const __nv_bfloat16* __restrict__ A2h, const __nv_bfloat16* __restrict__ A2l,
    const __nv_bfloat16* __restrict__ W2h, const __nv_bfloat16* __restrict__ W2l,
    const float* __restrict__ bias, const float* __restrict__ Hres,
    float* __restrict__ out,
    __nv_bfloat16* __restrict__ OutH, __nv_bfloat16* __restrict__ OutL, int N)
{
    __shared__ __align__(16) __nv_bfloat16 sA[2][128][SKW];
    __shared__ __align__(16) __nv_bfloat16 sB[2][128][SKW];

    int tid = threadIdx.x;
    int lane = tid & 31, w = tid >> 5;
    int warp_m = w & 3;
    int warp_n = w >> 2;
    int g = lane >> 2, tg = lane & 3;
    int row0 = blockIdx.x * 128;

    float acc[2][8][4];
    #pragma unroll
    for (int mf = 0; mf < 2; mf++)
        #pragma unroll
        for (int nf = 0; nf < 8; nf++)
            #pragma unroll
            for (int c = 0; c < 4; c++) acc[mf][nf][c] = 0.f;

    const __nv_bfloat16* As[6] = { A1h, A1l, A1h, A2h, A2l, A2h };
    const __nv_bfloat16* Bs[6] = { W1h, W1h, W1l, W2h, W2h, W2l };
    const int NC = DUAL ? 24 : 12;

    // prefetch coords: 2x16B for A, 2x16B for B per thread
    int pr = tid >> 2;
    int pc = tid & 3;

    auto prefetch = [&](int c, int buf) {
        const __nv_bfloat16* Ag = As[c >> 2];
        const __nv_bfloat16* Bg = Bs[c >> 2];
        int koff = (c & 3) * 32 + pc * 8;
        #pragma unroll
        for (int i = 0; i < 2; i++) {
            int r = pr + i * 64;
            int gr = row0 + r;
            cp_async16(&sA[buf][r][pc * 8], Ag + (size_t)gr * D + koff, gr < N);
            cp_async16(&sB[buf][r][pc * 8], Bg + (size_t)r * D + koff, true);
        }
        cp_commit();
    };

    // ldmatrix lane->address offsets (within a [128][SKW] bf16 array)
    int ra = (lane & 7) + (lane & 8);            // A row offset within 16-row frag
    int ca = (lane & 16) ? 8 : 0;                // A col offset (elems)
    int rb = (lane & 7) + ((lane & 16) ? 8 : 0); // B row offset within 16-n pair
    int cb = (lane & 8);                         // B col offset (elems)

    uint32_t baseA = (uint32_t)__cvta_generic_to_shared(
        &sA[0][warp_m * 32 + ra][ca]);
    uint32_t baseB = (uint32_t)__cvta_generic_to_shared(
        &sB[0][warp_n * 64 + rb][cb]);
    const uint32_t stageA = (uint32_t)(128 * SKW * sizeof(__nv_bfloat16));
    const uint32_t rowB = (uint32_t)(SKW * sizeof(__nv_bfloat16));

    prefetch(0, 0);

    #pragma unroll 1
    for (int c = 0; c < NC; c++) {
        cp_wait<0>();
        __syncthreads();
        if (c + 1 < NC) prefetch(c + 1, (c + 1) & 1);

        uint32_t aOff = baseA + (c & 1) * stageA;
        uint32_t bOff = baseB + (c & 1) * stageA;

        #pragma unroll
        for (int ks = 0; ks < 2; ks++) {
            uint32_t af[2][4];
            ldsm_x4(af[0], aOff + ks * 32);                    // rows +0..15
            ldsm_x4(af[1], aOff + 16 * rowB + ks * 32);        // rows +16..31
            uint32_t bf[4][4];
            #pragma unroll
            for (int np = 0; np < 4; np++)
                ldsm_x4(bf[np], bOff + np * 16 * rowB + ks * 32);
            #pragma unroll
            for (int mf = 0; mf < 2; mf++)
                #pragma unroll
                for (int np = 0; np < 4; np++) {
                    mma16816(acc[mf][np * 2 + 0],
                             af[mf][0], af[mf][1], af[mf][2], af[mf][3],
                             bf[np][0], bf[np][1]);
                    mma16816(acc[mf][np * 2 + 1],
                             af[mf][0], af[mf][1], af[mf][2], af[mf][3],
                             bf[np][2], bf[np][3]);
                }
        }
    }

    __syncthreads();

    // epilogue
    #pragma unroll
    for (int mf = 0; mf < 2; mf++) {
        #pragma unroll
        for (int half = 0; half < 2; half++) {
            int row = row0 + warp_m * 32 + mf * 16 + g + half * 8;
            if (row >= N) continue;
            #pragma unroll
            for (int nf = 0; nf < 8; nf++) {
                int col = warp_n * 64 + nf * 8 + tg * 2;
                float cx = acc[mf][nf][half * 2 + 0] + __ldg(bias + col);
                float cy = acc[mf][nf][half * 2 + 1] + __ldg(bias + col + 1);
                if (DUAL) {
                    float2 h2 = *(const float2*)(Hres + (size_t)row * D + col);
                    cx = fmaxf(cx, 0.f) + h2.x;
                    cy = fmaxf(cy, 0.f) + h2.y;
                }
                *(float2*)(out + (size_t)row * D + col) = make_float2(cx, cy);
                if (WRITE_BF16) {
                    uint32_t h, l;
                    split_pack2(cx, cy, h, l);
                    *(uint32_t*)(OutH + (size_t)row * D + col) = h;
                    *(uint32_t*)(OutL + (size_t)row * D + col) = l;
                }
            }
        }
    }
}

// ---------------- launch ----------------

extern "C" void kernel_launch(void* const* d_in, const int* in_sizes, int n_in,
                              void* d_out, int out_size)
{
    const float* x       = (const float*)d_in[0];
    const int*   ei      = (const int*)  d_in[1];
    const float* in_fc_w = (const float*)d_in[2];
    const float* in_fc_b = (const float*)d_in[3];
    const float* w_rel   = (const float*)d_in[4];
    const float* b_rel   = (const float*)d_in[5];
    const float* w_root  = (const float*)d_in[6];

    int N = in_sizes[0] / D;
    int E = in_sizes[1] / 2;
    const int* src = ei;
    const int* dst = ei + E;

    float* H;
    __nv_bfloat16 *Hh, *Hl, *AGGh, *AGGl, *Wh, *Wl;
    int *cnt, *row_ptr, *cursor, *adj;
    cudaGetSymbolAddress((void**)&H,       g_H);
    cudaGetSymbolAddress((void**)&Hh,      g_Hh);
    cudaGetSymbolAddress((void**)&Hl,      g_Hl);
    cudaGetSymbolAddress((void**)&AGGh,    g_AGGh);
    cudaGetSymbolAddress((void**)&AGGl,    g_AGGl);
    cudaGetSymbolAddress((void**)&Wh,      g_Wh);
    cudaGetSymbolAddress((void**)&Wl,      g_Wl);
    cudaGetSymbolAddress((void**)&cnt,     g_cnt);
    cudaGetSymbolAddress((void**)&row_ptr, g_row_ptr);
    cudaGetSymbolAddress((void**)&cursor,  g_cursor);
    cudaGetSymbolAddress((void**)&adj,     g_adj);

    int gblocks = (N + 127) / 128;
    int eblocks = (E + 255) / 256;
    int ablocks = (N * 32 + 255) / 256;

    // one-time conversions
    convert_w_kernel<<<(7 * D * D + 255) / 256, 256>>>(in_fc_w, w_rel, w_root, Wh, Wl);
    convert_x_kernel<<<(N * D / 4 + 255) / 256, 256>>>(x, AGGh, AGGl, N * D / 4);

    // CSR build (dst-sorted adjacency)
    zero_int_kernel<<<(N + 255) / 256, 256>>>(cnt, N);
    hist_kernel<<<eblocks, 256>>>(dst, cnt, E);
    scan_kernel<<<1, 1024>>>(cnt, row_ptr, cursor, N);
    fill_kernel<<<eblocks, 256>>>(src, dst, cursor, adj, E);

    // h = x @ in_fc_w + in_fc_b
    gemm_mma<false, true><<<gblocks, 256>>>(
        AGGh, AGGl, Wh, Wl,
        nullptr, nullptr, nullptr, nullptr,
        in_fc_b, nullptr, H, Hh, Hl, N);

    for (int l = 0; l < 3; l++) {
        aggregate_kernel<<<ablocks, 256>>>(H, row_ptr, adj, AGGh, AGGl, N);
        const __nv_bfloat16* W1h = Wh + (size_t)(1 + l) * D * D;
        const __nv_bfloat16* W1l = Wl + (size_t)(1 + l) * D * D;
        const __nv_bfloat16* W2h = Wh + (size_t)(4 + l) * D * D;
        const __nv_bfloat16* W2l = Wl + (size_t)(4 + l) * D * D;
        if (l < 2) {
            gemm_mma<true, true><<<gblocks, 256>>>(
                AGGh, AGGl, W1h, W1l, Hh, Hl, W2h, W2l,
                b_rel + (size_t)l * D, H, H, Hh, Hl, N);
        } else {
            gemm_mma<true, false><<<gblocks, 256>>>(
                AGGh, AGGl, W1h, W1l, Hh, Hl, W2h, W2l,
                b_rel + (size_t)l * D, H, (float*)d_out, nullptr, nullptr, N);
        }
    }
}

// round 8
// speedup vs baseline: 1.5906x; 1.2517x over previous
#include <cuda_runtime.h>
#include <cstdint>

#define D 128
#define MAXN 50000
#define MAXE 800000

// Scratch (allocation-free)
__device__ float g_H[MAXN * D];       // exact fp32 residual H
__device__ float g_Ht[MAXN * D];      // tf32-rounded H (root-term operand)
__device__ float g_AGG[MAXN * D];     // tf32-rounded agg (and rounded x for in_fc)
__device__ float g_Wt[7 * D * D];     // tf32-rounded weights, transposed [n][k]
__device__ int g_cnt[MAXN];
__device__ int g_row_ptr[MAXN + 1];
__device__ int g_cursor[MAXN];
__device__ int g_adj[MAXE];

// ---------------- helpers ----------------

__device__ __forceinline__ float tf32r(float x) {
    uint32_t u;
    asm("cvt.rna.tf32.f32 %0, %1;" : "=r"(u) : "f"(x));
    return __uint_as_float(u);
}

__device__ __forceinline__ void mma_tf32(float* d,
    uint32_t a0, uint32_t a1, uint32_t a2, uint32_t a3,
    uint32_t b0, uint32_t b1)
{
    asm volatile(
        "mma.sync.aligned.m16n8k8.row.col.f32.tf32.tf32.f32 "
        "{%0,%1,%2,%3}, {%4,%5,%6,%7}, {%8,%9}, {%0,%1,%2,%3};\n"
        : "+f"(d[0]), "+f"(d[1]), "+f"(d[2]), "+f"(d[3])
        : "r"(a0), "r"(a1), "r"(a2), "r"(a3), "r"(b0), "r"(b1));
}

__device__ __forceinline__ void cp_async16(void* smem_p, const void* gmem, bool pred)
{
    uint32_t s = (uint32_t)__cvta_generic_to_shared(smem_p);
    int sz = pred ? 16 : 0;
    asm volatile("cp.async.cg.shared.global [%0], [%1], 16, %2;\n"
                 :: "r"(s), "l"(gmem), "r"(sz));
}
__device__ __forceinline__ void cp_commit() {
    asm volatile("cp.async.commit_group;\n");
}
template <int N_>
__device__ __forceinline__ void cp_wait() {
    asm volatile("cp.async.wait_group %0;\n" :: "n"(N_));
}

// ---------------- conversion kernels ----------------

// W (7 DxD) -> transposed [n][k], tf32-rounded fp32
__global__ void __launch_bounds__(256) convert_w_kernel(
    const float* __restrict__ fw, const float* __restrict__ wrel,
    const float* __restrict__ wroot, float* __restrict__ Wt)
{
    int idx = blockIdx.x * 256 + threadIdx.x;
    if (idx >= 7 * D * D) return;
    int s = idx >> 14;
    int r = idx & 16383;
    int k = r >> 7;
    int n = r & 127;
    const float* srcm = (s == 0) ? fw
                      : (s < 4)  ? wrel + (size_t)(s - 1) * D * D
                                 : wroot + (size_t)(s - 4) * D * D;
    Wt[(size_t)s * D * D + n * D + k] = tf32r(srcm[k * D + n]);
}

// x -> tf32-rounded copy (into AGG buffer for in_fc's A operand)
__global__ void __launch_bounds__(256) round_x_kernel(
    const float* __restrict__ x, float* __restrict__ Xr, int n4)
{
    int i = blockIdx.x * 256 + threadIdx.x;
    if (i >= n4) return;
    float4 v = ((const float4*)x)[i];
    v.x = tf32r(v.x); v.y = tf32r(v.y); v.z = tf32r(v.z); v.w = tf32r(v.w);
    ((float4*)Xr)[i] = v;
}

// ---------------- CSR build ----------------

__global__ void __launch_bounds__(256) zero_int_kernel(int* __restrict__ p, int n) {
    int i = blockIdx.x * blockDim.x + threadIdx.x;
    for (; i < n; i += gridDim.x * blockDim.x) p[i] = 0;
}

__global__ void __launch_bounds__(256) hist_kernel(
    const int* __restrict__ dst, int* __restrict__ cnt, int E)
{
    int i = blockIdx.x * blockDim.x + threadIdx.x;
    for (; i < E; i += gridDim.x * blockDim.x)
        atomicAdd(&cnt[dst[i]], 1);
}

__global__ void __launch_bounds__(1024) scan_kernel(
    const int* __restrict__ cnt, int* __restrict__ row_ptr,
    int* __restrict__ cursor, int n)
{
    __shared__ int warp_sums[32];
    int tid = threadIdx.x;
    int chunk = (n + 1023) / 1024;
    int beg = tid * chunk;
    int end = min(beg + chunk, n);

    int local = 0;
    for (int i = beg; i < end; i++) local += cnt[i];

    int lane = tid & 31, w = tid >> 5;
    int v = local;
    #pragma unroll
    for (int o = 1; o < 32; o <<= 1) {
        int t = __shfl_up_sync(~0u, v, o);
        if (lane >= o) v += t;
    }
    if (lane == 31) warp_sums[w] = v;
    __syncthreads();
    if (w == 0) {
        int s = warp_sums[lane];
        #pragma unroll
        for (int o = 1; o < 32; o <<= 1) {
            int t = __shfl_up_sync(~0u, s, o);
            if (lane >= o) s += t;
        }
        warp_sums[lane] = s;
    }
    __syncthreads();

    int excl = v - local + (w > 0 ? warp_sums[w - 1] : 0);
    int run = excl;
    for (int i = beg; i < end; i++) {
        row_ptr[i] = run;
        cursor[i]  = run;
        run += cnt[i];
    }
    if (tid == 1023) row_ptr[n] = run;
}

__global__ void __launch_bounds__(256) fill_kernel(
    const int* __restrict__ src, const int* __restrict__ dst,
    int* __restrict__ cursor, int* __restrict__ adj, int E)
{
    int i = blockIdx.x * blockDim.x + threadIdx.x;
    for (; i < E; i += gridDim.x * blockDim.x) {
        int p = atomicAdd(&cursor[dst[i]], 1);
        adj[p] = src[i];
    }
}

// ---------------- gather-aggregate -> tf32-rounded fp32 ----------------

__global__ void __launch_bounds__(256) aggregate_kernel(
    const float* __restrict__ H, const int* __restrict__ row_ptr,
    const int* __restrict__ adj, float* __restrict__ AGG, int N)
{
    int node = (blockIdx.x * blockDim.x + threadIdx.x) >> 5;
    int lane = threadIdx.x & 31;
    if (node >= N) return;
    int beg = __ldg(row_ptr + node);
    int end = __ldg(row_ptr + node + 1);

    float4 acc = make_float4(0.f, 0.f, 0.f, 0.f);
    int e = beg;
    for (; e + 4 <= end; e += 4) {
        int s0 = __ldg(adj + e + 0);
        int s1 = __ldg(adj + e + 1);
        int s2 = __ldg(adj + e + 2);
        int s3 = __ldg(adj + e + 3);
        float4 v0 = __ldg((const float4*)(H + (size_t)s0 * D) + lane);
        float4 v1 = __ldg((const float4*)(H + (size_t)s1 * D) + lane);
        float4 v2 = __ldg((const float4*)(H + (size_t)s2 * D) + lane);
        float4 v3 = __ldg((const float4*)(H + (size_t)s3 * D) + lane);
        acc.x += v0.x + v1.x + v2.x + v3.x;
        acc.y += v0.y + v1.y + v2.y + v3.y;
        acc.z += v0.z + v1.z + v2.z + v3.z;
        acc.w += v0.w + v1.w + v2.w + v3.w;
    }
    for (; e < end; e++) {
        int s = __ldg(adj + e);
        float4 v = __ldg((const float4*)(H + (size_t)s * D) + lane);
        acc.x += v.x; acc.y += v.y; acc.z += v.z; acc.w += v.w;
    }
    acc.x = tf32r(acc.x); acc.y = tf32r(acc.y);
    acc.z = tf32r(acc.z); acc.w = tf32r(acc.w);
    ((float4*)(AGG + (size_t)node * D))[lane] = acc;
}

// ---------------- tensor-core GEMM (tf32 single-pass) ----------------
// Long-K view: NC chunks of K=32 tf32 (term t=c>>2, k-offset (c&3)*32).
// Block 256 thr = 8 warps (4x2), tile 128x128; warp 32x64.
// Per chunk: 4 k8-steps x (24 LDS + 16 HMMA.1688) per warp + 1 barrier.
// smem: 2 stages x (A 128x36f + B 128x36f) = 73728 B dynamic.

#define SK 36                     // f32 row stride (32 data + 4 pad)
#define TILE_F (128 * SK)
#define STAGE_F (2 * TILE_F)
#define GEMM_SMEM (2 * STAGE_F * 4)

template <bool DUAL, bool WRITE_RT>
__global__ void __launch_bounds__(256, 2) gemm_tf32(
    const float* __restrict__ A1, const float* __restrict__ W1,
    const float* __restrict__ A2, const float* __restrict__ W2,
    const float* __restrict__ bias, const float* __restrict__ Hres,
    float* __restrict__ out, float* __restrict__ OutRt, int N)
{
    extern __shared__ __align__(16) float sm[];

    int tid = threadIdx.x;
    int lane = tid & 31, w = tid >> 5;
    int warp_m = w & 3;
    int warp_n = w >> 2;
    int g = lane >> 2, tg = lane & 3;
    int row0 = blockIdx.x * 128;

    float acc[2][8][4];
    #pragma unroll
    for (int mf = 0; mf < 2; mf++)
        #pragma unroll
        for (int nf = 0; nf < 8; nf++)
            #pragma unroll
            for (int c = 0; c < 4; c++) acc[mf][nf][c] = 0.f;

    const int NC = DUAL ? 8 : 4;

    auto prefetch = [&](int c, int buf) {
        int t = c >> 2;
        int koff = (c & 3) * 32;
        const float* Ag = (DUAL && t) ? A2 : A1;
        const float* Bg = (DUAL && t) ? W2 : W1;
        float* base = sm + buf * STAGE_F;
        #pragma unroll
        for (int i = 0; i < 4; i++) {
            int idx = tid + i * 256;
            int r = idx >> 3, u = idx & 7;
            int gr = row0 + r;
            cp_async16(base + r * SK + u * 4,
                       Ag + (size_t)gr * D + koff + u * 4, gr < N);
            cp_async16(base + TILE_F + r * SK + u * 4,
                       Bg + (size_t)r * D + koff + u * 4, true);
        }
        cp_commit();
    };

    prefetch(0, 0);

    #pragma unroll 1
    for (int c = 0; c < NC; c++) {
        cp_wait<0>();
        __syncthreads();
        if (c + 1 < NC) prefetch(c + 1, (c + 1) & 1);

        const float* sa = sm + (c & 1) * STAGE_F;
        const float* sb = sa + TILE_F;

        #pragma unroll
        for (int ks = 0; ks < 4; ks++) {
            uint32_t bfr[8][2];
            #pragma unroll
            for (int nf = 0; nf < 8; nf++) {
                int n = warp_n * 64 + nf * 8 + g;
                bfr[nf][0] = __float_as_uint(sb[n * SK + ks * 8 + tg]);
                bfr[nf][1] = __float_as_uint(sb[n * SK + ks * 8 + tg + 4]);
            }
            #pragma unroll
            for (int mf = 0; mf < 2; mf++) {
                int r0 = warp_m * 32 + mf * 16 + g;
                uint32_t a0 = __float_as_uint(sa[r0 * SK + ks * 8 + tg]);
                uint32_t a1 = __float_as_uint(sa[(r0 + 8) * SK + ks * 8 + tg]);
                uint32_t a2 = __float_as_uint(sa[r0 * SK + ks * 8 + tg + 4]);
                uint32_t a3 = __float_as_uint(sa[(r0 + 8) * SK + ks * 8 + tg + 4]);
                #pragma unroll
                for (int nf = 0; nf < 8; nf++)
                    mma_tf32(acc[mf][nf], a0, a1, a2, a3,
                             bfr[nf][0], bfr[nf][1]);
            }
        }
    }

    __syncthreads();

    // epilogue: d0=D[g][2tg], d1=D[g][2tg+1], d2=D[g+8][2tg], d3=D[g+8][2tg+1]
    #pragma unroll
    for (int mf = 0; mf < 2; mf++) {
        #pragma unroll
        for (int half = 0; half < 2; half++) {
            int row = row0 + warp_m * 32 + mf * 16 + g + half * 8;
            if (row >= N) continue;
            #pragma unroll
            for (int nf = 0; nf < 8; nf++) {
                int col = warp_n * 64 + nf * 8 + tg * 2;
                float cx = acc[mf][nf][half * 2 + 0] + __ldg(bias + col);
                float cy = acc[mf][nf][half * 2 + 1] + __ldg(bias + col + 1);
                if (DUAL) {
                    float2 h2 = *(const float2*)(Hres + (size_t)row * D + col);
                    cx = fmaxf(cx, 0.f) + h2.x;
                    cy = fmaxf(cy, 0.f) + h2.y;
                }
                *(float2*)(out + (size_t)row * D + col) = make_float2(cx, cy);
                if (WRITE_RT) {
                    *(float2*)(OutRt + (size_t)row * D + col) =
                        make_float2(tf32r(cx), tf32r(cy));
                }
            }
        }
    }
}

// ---------------- launch ----------------

extern "C" void kernel_launch(void* const* d_in, const int* in_sizes, int n_in,
                              void* d_out, int out_size)
{
    const float* x       = (const float*)d_in[0];
    const int*   ei      = (const int*)  d_in[1];
    const float* in_fc_w = (const float*)d_in[2];
    const float* in_fc_b = (const float*)d_in[3];
    const float* w_rel   = (const float*)d_in[4];
    const float* b_rel   = (const float*)d_in[5];
    const float* w_root  = (const float*)d_in[6];

    int N = in_sizes[0] / D;
    int E = in_sizes[1] / 2;
    const int* src = ei;
    const int* dst = ei + E;

    float *H, *Ht, *AGG, *Wt;
    int *cnt, *row_ptr, *cursor, *adj;
    cudaGetSymbolAddress((void**)&H,       g_H);
    cudaGetSymbolAddress((void**)&Ht,      g_Ht);
    cudaGetSymbolAddress((void**)&AGG,     g_AGG);
    cudaGetSymbolAddress((void**)&Wt,      g_Wt);
    cudaGetSymbolAddress((void**)&cnt,     g_cnt);
    cudaGetSymbolAddress((void**)&row_ptr, g_row_ptr);
    cudaGetSymbolAddress((void**)&cursor,  g_cursor);
    cudaGetSymbolAddress((void**)&adj,     g_adj);

    cudaFuncSetAttribute(gemm_tf32<false, true>,
        cudaFuncAttributeMaxDynamicSharedMemorySize, GEMM_SMEM);
    cudaFuncSetAttribute(gemm_tf32<true, true>,
        cudaFuncAttributeMaxDynamicSharedMemorySize, GEMM_SMEM);
    cudaFuncSetAttribute(gemm_tf32<true, false>,
        cudaFuncAttributeMaxDynamicSharedMemorySize, GEMM_SMEM);

    int gblocks = (N + 127) / 128;
    int eblocks = (E + 255) / 256;
    int ablocks = (N * 32 + 255) / 256;

    // one-time conversions
    convert_w_kernel<<<(7 * D * D + 255) / 256, 256>>>(in_fc_w, w_rel, w_root, Wt);
    round_x_kernel<<<(N * D / 4 + 255) / 256, 256>>>(x, AGG, N * D / 4);

    // CSR build (dst-sorted adjacency)
    zero_int_kernel<<<(N + 255) / 256, 256>>>(cnt, N);
    hist_kernel<<<eblocks, 256>>>(dst, cnt, E);
    scan_kernel<<<1, 1024>>>(cnt, row_ptr, cursor, N);
    fill_kernel<<<eblocks, 256>>>(src, dst, cursor, adj, E);

    // h = x @ in_fc_w + in_fc_b   (A1 = rounded x staged in AGG)
    gemm_tf32<false, true><<<gblocks, 256, GEMM_SMEM>>>(
        AGG, Wt, nullptr, nullptr,
        in_fc_b, nullptr, H, Ht, N);

    for (int l = 0; l < 3; l++) {
        aggregate_kernel<<<ablocks, 256>>>(H, row_ptr, adj, AGG, N);
        const float* W1 = Wt + (size_t)(1 + l) * D * D;
        const float* W2 = Wt + (size_t)(4 + l) * D * D;
        if (l < 2) {
            gemm_tf32<true, true><<<gblocks, 256, GEMM_SMEM>>>(
                AGG, W1, Ht, W2,
                b_rel + (size_t)l * D, H, H, Ht, N);
        } else {
            gemm_tf32<true, false><<<gblocks, 256, GEMM_SMEM>>>(
                AGG, W1, Ht, W2,
                b_rel + (size_t)l * D, H, (float*)d_out, nullptr, N);
        }
    }
}